// round 4
// baseline (speedup 1.0000x reference)
#include <cuda_runtime.h>
#include <cuda_bf16.h>

// Problem shape (fixed by the dataset)
#define Bv 8
#define Cv 256
#define Lv 4096
#define Kv 8
#define Gv 4              // channels per CTA (share w loads)
#define TPB 256
#define CHUNKS 4          // L is split into 4 chunks of 1024 elements
#define CPG (Cv / Gv)     // 64 channel-groups per batch

// Transposed softmax time-weights: g_wt[k][b][l] (1 MB, L2-resident).
__device__ float g_wt[Kv * Bv * Lv];
// Deterministic Gram partials: per (b,c) row, per chunk, {g00,g01,g11}. 96 KB.
__device__ float g_part[Bv * Cv * CHUNKS * 3];

// ---------------------------------------------------------------------------
// Kernel W: w[b,l,k] = softmax_k( dt[b,l-k] - dt[b,l] ), scattered to k-planes.
// BIG-sentinel semantics: for l < K-1 all valid weights are exactly 0.
// ---------------------------------------------------------------------------
__global__ void __launch_bounds__(256) compute_w_kernel(const float* __restrict__ dt) {
    int idx = blockIdx.x * blockDim.x + threadIdx.x;   // idx = b*L + l
    if (idx >= Bv * Lv) return;
    int l = idx & (Lv - 1);
    int b = idx >> 12;

    if (l < Kv - 1) {
#pragma unroll
        for (int k = 0; k < Kv; k++)
            g_wt[(k * Bv + b) * Lv + l] = 0.0f;
        return;
    }

    float base = dt[idx];
    float d[Kv];
    float mx = -1e30f;
#pragma unroll
    for (int k = 0; k < Kv; k++) {
        d[k] = dt[idx - k] - base;
        mx = fmaxf(mx, d[k]);
    }
    float s = 0.0f;
#pragma unroll
    for (int k = 0; k < Kv; k++) {
        d[k] = __expf(d[k] - mx);
        s += d[k];
    }
    float inv = 1.0f / s;
#pragma unroll
    for (int k = 0; k < Kv; k++)
        g_wt[(k * Bv + b) * Lv + l] = d[k] * inv;
}

// ---------------------------------------------------------------------------
// Shared helper: load w (8 taps x 4 elems) + x window, produce at/ap for the
// 4 consecutive elements starting at 4*j of channel row xr.
// xw[m] = x[4j - 8 + m], m = 0..11.
// ---------------------------------------------------------------------------
__device__ __forceinline__ void load_xwindow(const float4* __restrict__ xr, int j,
                                             float* __restrict__ xw) {
    float4 z = make_float4(0.f, 0.f, 0.f, 0.f);
    float4 xm2 = (j >= 2) ? xr[j - 2] : z;
    float4 xm1 = (j >= 1) ? xr[j - 1] : z;
    float4 x0  = xr[j];
    xw[0] = xm2.x; xw[1] = xm2.y; xw[2]  = xm2.z; xw[3]  = xm2.w;
    xw[4] = xm1.x; xw[5] = xm1.y; xw[6]  = xm1.z; xw[7]  = xm1.w;
    xw[8] = x0.x;  xw[9] = x0.y;  xw[10] = x0.z;  xw[11] = x0.w;
}

// ---------------------------------------------------------------------------
// Kernel A: Gram partials. Grid (CHUNKS, CPG, Bv), 256 threads.
// Each thread: one float4 (4 elements) for each of Gv channels.
// w loaded once per thread (8 coalesced LDG.128), reused by all channels.
// ---------------------------------------------------------------------------
__global__ void __launch_bounds__(TPB) gram_kernel(
    const float* __restrict__ x,
    const float* __restrict__ kt)
{
    __shared__ float sred[Gv][8][3];

    const int chunk = blockIdx.x;
    const int cg    = blockIdx.y;
    const int b     = blockIdx.z;
    const int tid   = threadIdx.x;
    const int lid   = tid & 31;
    const int wid   = tid >> 5;
    const int j     = chunk * TPB + tid;      // float4 index within row

    float ktr[Kv];
#pragma unroll
    for (int k = 0; k < Kv; k++) ktr[k] = __ldg(&kt[k]);

    float4 wk[Kv];
#pragma unroll
    for (int k = 0; k < Kv; k++)
        wk[k] = ((const float4*)&g_wt[(size_t)(k * Bv + b) * Lv])[j];
    const float* wkf = (const float*)wk;      // wkf[k*4 + c]

#pragma unroll
    for (int g = 0; g < Gv; g++) {
        const float4* xr = (const float4*)(x + (size_t)(b * Cv + cg * Gv + g) * Lv);
        float xw[12];
        load_xwindow(xr, j, xw);

        float g00 = 0.f, g01 = 0.f, g11 = 0.f;
#pragma unroll
        for (int c = 0; c < 4; c++) {
            float a_t = 0.f, a_p = 0.f;
#pragma unroll
            for (int k = 0; k < Kv; k++) {
                float xv = xw[8 + c - k];
                a_t = fmaf(wkf[k * 4 + c], xv, a_t);
                a_p = fmaf(ktr[k],        xv, a_p);
            }
            g00 = fmaf(a_t, a_t, g00);
            g01 = fmaf(a_t, a_p, g01);
            g11 = fmaf(a_p, a_p, g11);
        }
#pragma unroll
        for (int o = 16; o > 0; o >>= 1) {
            g00 += __shfl_xor_sync(0xffffffffu, g00, o);
            g01 += __shfl_xor_sync(0xffffffffu, g01, o);
            g11 += __shfl_xor_sync(0xffffffffu, g11, o);
        }
        if (lid == 0) {
            sred[g][wid][0] = g00;
            sred[g][wid][1] = g01;
            sred[g][wid][2] = g11;
        }
    }
    __syncthreads();

    if (tid < Gv * 3) {
        int g = tid / 3, q = tid - g * 3;
        float s = 0.f;
#pragma unroll
        for (int wq = 0; wq < 8; wq++) s += sred[g][wq][q];
        int row = b * Cv + cg * Gv + g;
        g_part[(row * CHUNKS + chunk) * 3 + q] = s;
    }
}

// ---------------------------------------------------------------------------
// Kernel C: output. Same grid. Each CTA sums the 4 chunk-partials for its
// 4 channels, derives the 2x2-softmax coefficients, recomputes at/ap, and
// writes out = ca*at + cb*ap (coalesced STG.128).
// ---------------------------------------------------------------------------
__global__ void __launch_bounds__(TPB) out_kernel(
    const float* __restrict__ x,
    const float* __restrict__ kt,
    float* __restrict__ out)
{
    __shared__ float scoef[Gv][2];

    const int chunk = blockIdx.x;
    const int cg    = blockIdx.y;
    const int b     = blockIdx.z;
    const int tid   = threadIdx.x;
    const int j     = chunk * TPB + tid;

    if (tid < Gv) {
        const float* p = &g_part[((b * Cv + cg * Gv + tid) * CHUNKS) * 3];
        float G00 = 0.f, G01 = 0.f, G11 = 0.f;
#pragma unroll
        for (int ch = 0; ch < CHUNKS; ch++) {
            G00 += p[ch * 3 + 0];
            G01 += p[ch * 3 + 1];
            G11 += p[ch * 3 + 2];
        }
        // scores row0 = softmax([G00,G01]); row1 = softmax([G01,G11])
        // out = 0.5*((s00+s10)*at + ((1-s00)+(1-s10))*ap)
        float s00 = 1.0f / (1.0f + __expf(G01 - G00));
        float s10 = 1.0f / (1.0f + __expf(G11 - G01));
        scoef[tid][0] = 0.5f * (s00 + s10);
        scoef[tid][1] = 0.5f * ((1.0f - s00) + (1.0f - s10));
    }

    float ktr[Kv];
#pragma unroll
    for (int k = 0; k < Kv; k++) ktr[k] = __ldg(&kt[k]);

    float4 wk[Kv];
#pragma unroll
    for (int k = 0; k < Kv; k++)
        wk[k] = ((const float4*)&g_wt[(size_t)(k * Bv + b) * Lv])[j];
    const float* wkf = (const float*)wk;

    __syncthreads();

#pragma unroll
    for (int g = 0; g < Gv; g++) {
        const size_t row = (size_t)(b * Cv + cg * Gv + g) * Lv;
        const float4* xr = (const float4*)(x + row);
        float xw[12];
        load_xwindow(xr, j, xw);

        const float ca = scoef[g][0];
        const float cb = scoef[g][1];
        float4 o;
        float* of = (float*)&o;
#pragma unroll
        for (int c = 0; c < 4; c++) {
            float a_t = 0.f, a_p = 0.f;
#pragma unroll
            for (int k = 0; k < Kv; k++) {
                float xv = xw[8 + c - k];
                a_t = fmaf(wkf[k * 4 + c], xv, a_t);
                a_p = fmaf(ktr[k],        xv, a_p);
            }
            of[c] = fmaf(ca, a_t, cb * a_p);
        }
        ((float4*)(out + row))[j] = o;
    }
}

// ---------------------------------------------------------------------------
extern "C" void kernel_launch(void* const* d_in, const int* in_sizes, int n_in,
                              void* d_out, int out_size) {
    const float* x  = (const float*)d_in[0];   // (B, C, L) f32
    const float* dt = (const float*)d_in[1];   // (B, L)    f32
    const float* kt = (const float*)d_in[2];   // (1, 1, K) f32
    float* out = (float*)d_out;                // (B, C, L) f32

    dim3 grid(CHUNKS, CPG, Bv);                // 4 x 64 x 8 = 2048 CTAs

    compute_w_kernel<<<(Bv * Lv + 255) / 256, 256>>>(dt);
    gram_kernel<<<grid, TPB>>>(x, kt);
    out_kernel<<<grid, TPB>>>(x, kt, out);
}

// round 5
// speedup vs baseline: 1.2243x; 1.2243x over previous
#include <cuda_runtime.h>
#include <cuda_bf16.h>

// Problem shape (fixed by the dataset)
#define Bv 8
#define Cv 256
#define Lv 4096
#define Kv 8
#define Gv 2              // channels per CTA (share w loads)
#define TPB 256
#define NJ (Lv / 4)       // float4s per row = 1024
#define ITERS (NJ / TPB)  // 4

// Transposed softmax time-weights: g_wt[k][b][l] (1 MB, L2-resident).
// Plane-major so per-tap loads are lane-contiguous (coalesced LDG.128).
__device__ float g_wt[Kv * Bv * Lv];

// ---------------------------------------------------------------------------
// Kernel W: w[b,l,k] = softmax_k( dt[b,l-k] - dt[b,l] ), scattered to k-planes.
// BIG-sentinel semantics: for l < K-1 all valid weights are exactly 0.
// ---------------------------------------------------------------------------
__global__ void __launch_bounds__(256) compute_w_kernel(const float* __restrict__ dt) {
    int idx = blockIdx.x * blockDim.x + threadIdx.x;   // idx = b*L + l
    if (idx >= Bv * Lv) return;
    int l = idx & (Lv - 1);
    int b = idx >> 12;

    if (l < Kv - 1) {
#pragma unroll
        for (int k = 0; k < Kv; k++)
            g_wt[(k * Bv + b) * Lv + l] = 0.0f;
        return;
    }

    float base = dt[idx];
    float d[Kv];
    float mx = -1e30f;
#pragma unroll
    for (int k = 0; k < Kv; k++) {
        d[k] = dt[idx - k] - base;
        mx = fmaxf(mx, d[k]);
    }
    float s = 0.0f;
#pragma unroll
    for (int k = 0; k < Kv; k++) {
        d[k] = __expf(d[k] - mx);
        s += d[k];
    }
    float inv = 1.0f / s;
#pragma unroll
    for (int k = 0; k < Kv; k++)
        g_wt[(k * Bv + b) * Lv + l] = d[k] * inv;
}

// ---------------------------------------------------------------------------
// Fused kernel: one CTA per 2 channels of one batch. 256 threads, 3 CTAs/SM.
//   Pass 1: per float4 j (4 per thread): load w (8 coalesced LDG.128, shared
//           by both channels), x window via predicated LDG.128 (L1-hot halo),
//           compute at/ap -> smem (STS.128), accumulate Gram partials.
//   Reduce: 6 scalars -> 2x2 softmax -> per-channel coefficients.
//   Pass 2: out = ca*at + cb*ap from smem (LDS.128 -> STG.128).
// Dynamic smem: sat[2][NJ] + sap[2][NJ] float4 = 65536 B.
// ---------------------------------------------------------------------------
#define SMEM_BYTES (2 * Gv * Lv * 4)

__global__ void __launch_bounds__(TPB, 3) fused_kernel(
    const float* __restrict__ x,
    const float* __restrict__ kt,
    float* __restrict__ out)
{
    extern __shared__ float smem[];
    float4* sat = (float4*)smem;               // [Gv][NJ]
    float4* sap = (float4*)(smem + Gv * Lv);   // [Gv][NJ]
    __shared__ float sred[8][Gv * 3];
    __shared__ float scoef[Gv][2];

    const int b   = blockIdx.x >> 7;           // / (Cv/Gv = 128)
    const int c0  = (blockIdx.x & 127) * Gv;
    const int tid = threadIdx.x;
    const int lid = tid & 31;
    const int wid = tid >> 5;

    float ktr[Kv];
#pragma unroll
    for (int k = 0; k < Kv; k++) ktr[k] = __ldg(&kt[k]);

    float gr[Gv][3];
#pragma unroll
    for (int g = 0; g < Gv; g++) { gr[g][0] = 0.f; gr[g][1] = 0.f; gr[g][2] = 0.f; }

    const float4 zero4 = make_float4(0.f, 0.f, 0.f, 0.f);

#pragma unroll 1
    for (int i = 0; i < ITERS; i++) {
        const int j = tid + i * TPB;           // float4 index within row

        // w for elements 4j..4j+3, all 8 taps (coalesced, plane-major).
        float4 wk[Kv];
#pragma unroll
        for (int k = 0; k < Kv; k++)
            wk[k] = ((const float4*)&g_wt[(size_t)(k * Bv + b) * Lv])[j];
        const float* wkf = (const float*)wk;   // wkf[k*4 + c]

#pragma unroll
        for (int g = 0; g < Gv; g++) {
            const float4* xr = (const float4*)(x + (size_t)(b * Cv + c0 + g) * Lv);
            float4 xm2 = (j >= 2) ? xr[j - 2] : zero4;
            float4 xm1 = (j >= 1) ? xr[j - 1] : zero4;
            float4 x0  = xr[j];
            float xw[12] = {xm2.x, xm2.y, xm2.z, xm2.w,
                            xm1.x, xm1.y, xm1.z, xm1.w,
                            x0.x,  x0.y,  x0.z,  x0.w};

            float4 atv, apv;
            float* atf = (float*)&atv;
            float* apf = (float*)&apv;
#pragma unroll
            for (int c = 0; c < 4; c++) {
                float a_t = 0.f, a_p = 0.f;
#pragma unroll
                for (int k = 0; k < Kv; k++) {
                    float xv = xw[8 + c - k];
                    a_t = fmaf(wkf[k * 4 + c], xv, a_t);
                    a_p = fmaf(ktr[k],        xv, a_p);
                }
                atf[c] = a_t;
                apf[c] = a_p;
                gr[g][0] = fmaf(a_t, a_t, gr[g][0]);
                gr[g][1] = fmaf(a_t, a_p, gr[g][1]);
                gr[g][2] = fmaf(a_p, a_p, gr[g][2]);
            }
            sat[g * NJ + j] = atv;
            sap[g * NJ + j] = apv;
        }
    }

    // ---- block reduction of 6 Gram scalars ----
#pragma unroll
    for (int g = 0; g < Gv; g++) {
#pragma unroll
        for (int q = 0; q < 3; q++) {
            float v = gr[g][q];
#pragma unroll
            for (int o = 16; o > 0; o >>= 1)
                v += __shfl_xor_sync(0xffffffffu, v, o);
            if (lid == 0) sred[wid][g * 3 + q] = v;
        }
    }
    __syncthreads();
    if (tid < Gv) {
        float G00 = 0.f, G01 = 0.f, G11 = 0.f;
#pragma unroll
        for (int wq = 0; wq < 8; wq++) {
            G00 += sred[wq][tid * 3 + 0];
            G01 += sred[wq][tid * 3 + 1];
            G11 += sred[wq][tid * 3 + 2];
        }
        // scores row0 = softmax([G00,G01]); row1 = softmax([G01,G11])
        // out = 0.5*((s00+s10)*at + ((1-s00)+(1-s10))*ap)
        float s00 = 1.0f / (1.0f + __expf(G01 - G00));
        float s10 = 1.0f / (1.0f + __expf(G11 - G01));
        scoef[tid][0] = 0.5f * (s00 + s10);
        scoef[tid][1] = 0.5f * ((1.0f - s00) + (1.0f - s10));
    }
    __syncthreads();

    // ---- pass 2: out = ca*at + cb*ap (LDS.128 -> STG.128) ----
#pragma unroll
    for (int g = 0; g < Gv; g++) {
        const float ca = scoef[g][0];
        const float cb = scoef[g][1];
        float4* orow = (float4*)(out + (size_t)(b * Cv + c0 + g) * Lv);
#pragma unroll
        for (int i = 0; i < ITERS; i++) {
            const int j = tid + i * TPB;
            float4 a = sat[g * NJ + j];
            float4 p = sap[g * NJ + j];
            float4 o;
            o.x = fmaf(ca, a.x, cb * p.x);
            o.y = fmaf(ca, a.y, cb * p.y);
            o.z = fmaf(ca, a.z, cb * p.z);
            o.w = fmaf(ca, a.w, cb * p.w);
            orow[j] = o;
        }
    }
}

// ---------------------------------------------------------------------------
extern "C" void kernel_launch(void* const* d_in, const int* in_sizes, int n_in,
                              void* d_out, int out_size) {
    const float* x  = (const float*)d_in[0];   // (B, C, L) f32
    const float* dt = (const float*)d_in[1];   // (B, L)    f32
    const float* kt = (const float*)d_in[2];   // (1, 1, K) f32
    float* out = (float*)d_out;                // (B, C, L) f32

    cudaFuncSetAttribute(fused_kernel,
                         cudaFuncAttributeMaxDynamicSharedMemorySize, SMEM_BYTES);

    compute_w_kernel<<<(Bv * Lv + 255) / 256, 256>>>(dt);
    fused_kernel<<<Bv * Cv / Gv, TPB, SMEM_BYTES>>>(x, kt, out);
}

// round 6
// speedup vs baseline: 1.2344x; 1.0082x over previous
#include <cuda_runtime.h>
#include <cuda_bf16.h>

// Problem shape (fixed by the dataset)
#define Bv 8
#define Cv 256
#define Lv 4096
#define Kv 8
#define Gv 2              // channels per CTA (share weight computation)
#define TPB 256
#define NJ (Lv / 4)       // float4s per row = 1024
#define ITERS (NJ / TPB)  // 4

// ---------------------------------------------------------------------------
// Single fused kernel: one CTA per 2 channels of one batch. 256 thr, 3 CTA/SM.
// The softmax time-weights are computed INLINE from the dt window (no
// precompute kernel, no global weight array):
//   w_k(l) ∝ exp(dt[l-k] - dt[l])   (dt ∈ [0,1) -> exps bounded, no max shift)
//   at[l]  = (Σ_k exp(d_k) x[l-k]) * (1/Σ_k exp(d_k));  at[l<7] = 0 (BIG mask)
//   ap[l]  = Σ_k kt[k] x[l-k]       (x[<0] = 0)
// Pass 1 writes at/ap to smem and accumulates the 2x2 Gram; after the block
// reduction the 2x2 softmax gives scalar coefficients; pass 2 emits
// out = ca*at + cb*ap.
// Dynamic smem: sat[2][NJ] + sap[2][NJ] float4 = 65536 B.
// ---------------------------------------------------------------------------
#define SMEM_BYTES (2 * Gv * Lv * 4)

__global__ void __launch_bounds__(TPB, 3) fused_kernel(
    const float* __restrict__ x,
    const float* __restrict__ dt,
    const float* __restrict__ kt,
    float* __restrict__ out)
{
    extern __shared__ float smem[];
    float4* sat = (float4*)smem;               // [Gv][NJ]
    float4* sap = (float4*)(smem + Gv * Lv);   // [Gv][NJ]
    __shared__ float sred[8][Gv * 3];
    __shared__ float scoef[Gv][2];

    const int b   = blockIdx.x >> 7;           // / (Cv/Gv = 128)
    const int c0  = (blockIdx.x & 127) * Gv;
    const int tid = threadIdx.x;
    const int lid = tid & 31;
    const int wid = tid >> 5;

    const float4* dtr = (const float4*)(dt + (size_t)b * Lv);

    float ktr[Kv];
#pragma unroll
    for (int k = 0; k < Kv; k++) ktr[k] = __ldg(&kt[k]);

    float gr[Gv][3];
#pragma unroll
    for (int g = 0; g < Gv; g++) { gr[g][0] = 0.f; gr[g][1] = 0.f; gr[g][2] = 0.f; }

    const float4 zero4 = make_float4(0.f, 0.f, 0.f, 0.f);

#pragma unroll 1
    for (int i = 0; i < ITERS; i++) {
        const int j = tid + i * TPB;           // float4 index within row

        // ---- dt window [4j-8 .. 4j+3] (zero-fill left of row start) ----
        float dtw[12];
        {
            float4 m2 = (j >= 2) ? dtr[j - 2] : zero4;
            float4 m1 = (j >= 1) ? dtr[j - 1] : zero4;
            float4 d0 = dtr[j];
            dtw[0] = m2.x; dtw[1] = m2.y; dtw[2]  = m2.z; dtw[3]  = m2.w;
            dtw[4] = m1.x; dtw[5] = m1.y; dtw[6]  = m1.z; dtw[7]  = m1.w;
            dtw[8] = d0.x; dtw[9] = d0.y; dtw[10] = d0.z; dtw[11] = d0.w;
        }

        // ---- unnormalized softmax weights + reciprocal sums (shared by
        //      both channels) ----
        float ew[4][Kv];
        float inv[4];
#pragma unroll
        for (int c = 0; c < 4; c++) {
            float base = dtw[8 + c];
            float s = 0.f;
#pragma unroll
            for (int k = 0; k < Kv; k++) {
                float e = __expf(dtw[8 + c - k] - base);
                ew[c][k] = e;
                s += e;
            }
            inv[c] = __fdividef(1.0f, s);
        }

#pragma unroll
        for (int g = 0; g < Gv; g++) {
            const float4* xr = (const float4*)(x + (size_t)(b * Cv + c0 + g) * Lv);
            float4 xm2 = (j >= 2) ? xr[j - 2] : zero4;
            float4 xm1 = (j >= 1) ? xr[j - 1] : zero4;
            float4 x0  = xr[j];
            float xw[12] = {xm2.x, xm2.y, xm2.z, xm2.w,
                            xm1.x, xm1.y, xm1.z, xm1.w,
                            x0.x,  x0.y,  x0.z,  x0.w};

            float4 atv, apv;
            float* atf = (float*)&atv;
            float* apf = (float*)&apv;
#pragma unroll
            for (int c = 0; c < 4; c++) {
                float a_t = 0.f, a_p = 0.f;
#pragma unroll
                for (int k = 0; k < Kv; k++) {
                    float xv = xw[8 + c - k];
                    a_t = fmaf(ew[c][k], xv, a_t);
                    a_p = fmaf(ktr[k],   xv, a_p);
                }
                a_t *= inv[c];
                // BIG-sentinel semantics: average_time == 0 exactly for l < K-1
                if (j < 2 && 4 * j + c < Kv - 1) a_t = 0.f;
                atf[c] = a_t;
                apf[c] = a_p;
                gr[g][0] = fmaf(a_t, a_t, gr[g][0]);
                gr[g][1] = fmaf(a_t, a_p, gr[g][1]);
                gr[g][2] = fmaf(a_p, a_p, gr[g][2]);
            }
            sat[g * NJ + j] = atv;
            sap[g * NJ + j] = apv;
        }
    }

    // ---- block reduction of 6 Gram scalars ----
#pragma unroll
    for (int g = 0; g < Gv; g++) {
#pragma unroll
        for (int q = 0; q < 3; q++) {
            float v = gr[g][q];
#pragma unroll
            for (int o = 16; o > 0; o >>= 1)
                v += __shfl_xor_sync(0xffffffffu, v, o);
            if (lid == 0) sred[wid][g * 3 + q] = v;
        }
    }
    __syncthreads();
    if (tid < Gv) {
        float G00 = 0.f, G01 = 0.f, G11 = 0.f;
#pragma unroll
        for (int wq = 0; wq < 8; wq++) {
            G00 += sred[wq][tid * 3 + 0];
            G01 += sred[wq][tid * 3 + 1];
            G11 += sred[wq][tid * 3 + 2];
        }
        // scores row0 = softmax([G00,G01]); row1 = softmax([G01,G11])
        // out = 0.5*((s00+s10)*at + ((1-s00)+(1-s10))*ap)
        float s00 = 1.0f / (1.0f + __expf(G01 - G00));
        float s10 = 1.0f / (1.0f + __expf(G11 - G01));
        scoef[tid][0] = 0.5f * (s00 + s10);
        scoef[tid][1] = 0.5f * ((1.0f - s00) + (1.0f - s10));
    }
    __syncthreads();

    // ---- pass 2: out = ca*at + cb*ap (LDS.128 -> STG.128) ----
#pragma unroll
    for (int g = 0; g < Gv; g++) {
        const float ca = scoef[g][0];
        const float cb = scoef[g][1];
        float4* orow = (float4*)(out + (size_t)(b * Cv + c0 + g) * Lv);
#pragma unroll
        for (int i = 0; i < ITERS; i++) {
            const int j = tid + i * TPB;
            float4 a = sat[g * NJ + j];
            float4 p = sap[g * NJ + j];
            float4 o;
            o.x = fmaf(ca, a.x, cb * p.x);
            o.y = fmaf(ca, a.y, cb * p.y);
            o.z = fmaf(ca, a.z, cb * p.z);
            o.w = fmaf(ca, a.w, cb * p.w);
            orow[j] = o;
        }
    }
}

// ---------------------------------------------------------------------------
extern "C" void kernel_launch(void* const* d_in, const int* in_sizes, int n_in,
                              void* d_out, int out_size) {
    const float* x  = (const float*)d_in[0];   // (B, C, L) f32
    const float* dt = (const float*)d_in[1];   // (B, L)    f32
    const float* kt = (const float*)d_in[2];   // (1, 1, K) f32
    float* out = (float*)d_out;                // (B, C, L) f32

    cudaFuncSetAttribute(fused_kernel,
                         cudaFuncAttributeMaxDynamicSharedMemorySize, SMEM_BYTES);

    fused_kernel<<<Bv * Cv / Gv, TPB, SMEM_BYTES>>>(x, dt, kt, out);
}

// round 7
// speedup vs baseline: 1.4844x; 1.2025x over previous
#include <cuda_runtime.h>
#include <cuda_bf16.h>

// Problem shape (fixed by the dataset)
#define Bv 8
#define Cv 256
#define Lv 4096
#define Kv 8
#define Gv 2              // channels per CTA (share weight computation)
#define TPB 256
#define NJ (Lv / 4)       // float4s per row = 1024
#define ITERS (NJ / TPB)  // 4

#define SMEM_BYTES (2 * Gv * Lv * 4)

// ---------------------------------------------------------------------------
// Softmax identity: w_k(l) = exp(dt[l-k]-dt[l])/Z = E[l-k]/sum_k' E[l-k'],
// E = exp(dt). The base exp(-dt[l]) cancels -> 12 exps per 4 elements instead
// of 32. at[l] = (sum_k E[l-k] x[l-k]) * rcp(sum_k E[l-k]); at[l<7] = 0 (the
// reference's BIG sentinel makes average_time exactly 0 there).
// ---------------------------------------------------------------------------
template<bool FIRST>
__device__ __forceinline__ void pass1_iter(
    const int j,
    const float4* __restrict__ dtr,
    const float4* __restrict__ xr0,
    const float4* __restrict__ xr1,
    const float*  __restrict__ ktr,     // [Kv] in registers
    float4* __restrict__ sat,           // [Gv*NJ]
    float4* __restrict__ sap,           // [Gv*NJ]
    float*  __restrict__ gr)            // [Gv*3] Gram accumulators
{
    const float4 zero4 = make_float4(0.f, 0.f, 0.f, 0.f);

    // dt window [4j-8 .. 4j+3]
    float4 dm2 = FIRST ? ((j >= 2) ? dtr[j - 2] : zero4) : dtr[j - 2];
    float4 dm1 = FIRST ? ((j >= 1) ? dtr[j - 1] : zero4) : dtr[j - 1];
    float4 dd0 = dtr[j];
    float Ew[12] = {dm2.x, dm2.y, dm2.z, dm2.w,
                    dm1.x, dm1.y, dm1.z, dm1.w,
                    dd0.x, dd0.y, dd0.z, dd0.w};
#pragma unroll
    for (int m = 0; m < 12; m++) Ew[m] = __expf(Ew[m]);

    // reciprocal of the 8-tap sums (factored partials to cut adds)
    float core = ((Ew[4] + Ew[5]) + (Ew[6] + Ew[7])) + Ew[8];   // E[4..8]
    float p23  = Ew[2] + Ew[3];
    float p910 = Ew[9] + Ew[10];
    float inv0 = __fdividef(1.0f, core + (Ew[1] + p23));        // E[1..8]
    float inv1 = __fdividef(1.0f, core + (p23 + Ew[9]));        // E[2..9]
    float inv2 = __fdividef(1.0f, core + (Ew[3] + p910));       // E[3..10]
    float inv3 = __fdividef(1.0f, core + (p910 + Ew[11]));      // E[4..11]
    float inv[4] = {inv0, inv1, inv2, inv3};

#pragma unroll
    for (int g = 0; g < Gv; g++) {
        const float4* xr = (g == 0) ? xr0 : xr1;
        float4 xm2 = FIRST ? ((j >= 2) ? xr[j - 2] : zero4) : xr[j - 2];
        float4 xm1 = FIRST ? ((j >= 1) ? xr[j - 1] : zero4) : xr[j - 1];
        float4 x0  = xr[j];
        float xw[12] = {xm2.x, xm2.y, xm2.z, xm2.w,
                        xm1.x, xm1.y, xm1.z, xm1.w,
                        x0.x,  x0.y,  x0.z,  x0.w};

        float4 atv, apv;
        float* atf = (float*)&atv;
        float* apf = (float*)&apv;
#pragma unroll
        for (int c = 0; c < 4; c++) {
            float num = 0.f, a_p = 0.f;
#pragma unroll
            for (int k = 0; k < Kv; k++) {
                int m = 8 + c - k;
                num = fmaf(Ew[m],  xw[m], num);
                a_p = fmaf(ktr[k], xw[m], a_p);
            }
            float a_t = num * inv[c];
            if (FIRST) {
                if (4 * j + c < Kv - 1) a_t = 0.f;   // BIG-sentinel mask
            }
            atf[c] = a_t;
            apf[c] = a_p;
            gr[g * 3 + 0] = fmaf(a_t, a_t, gr[g * 3 + 0]);
            gr[g * 3 + 1] = fmaf(a_t, a_p, gr[g * 3 + 1]);
            gr[g * 3 + 2] = fmaf(a_p, a_p, gr[g * 3 + 2]);
        }
        sat[g * NJ + j] = atv;
        sap[g * NJ + j] = apv;
    }
}

__global__ void __launch_bounds__(TPB, 3) fused_kernel(
    const float* __restrict__ x,
    const float* __restrict__ dt,
    const float* __restrict__ kt,
    float* __restrict__ out)
{
    extern __shared__ float smem[];
    float4* sat = (float4*)smem;               // [Gv][NJ]
    float4* sap = (float4*)(smem + Gv * Lv);   // [Gv][NJ]
    __shared__ float sred[8][Gv * 3];
    __shared__ float scoef[Gv][2];

    const int b   = blockIdx.x >> 7;           // / (Cv/Gv = 128)
    const int c0  = (blockIdx.x & 127) * Gv;
    const int tid = threadIdx.x;
    const int lid = tid & 31;
    const int wid = tid >> 5;

    const float4* dtr = (const float4*)(dt + (size_t)b * Lv);
    const float4* xr0 = (const float4*)(x + (size_t)(b * Cv + c0 + 0) * Lv);
    const float4* xr1 = (const float4*)(x + (size_t)(b * Cv + c0 + 1) * Lv);

    float ktr[Kv];
#pragma unroll
    for (int k = 0; k < Kv; k++) ktr[k] = __ldg(&kt[k]);

    float gr[Gv * 3];
#pragma unroll
    for (int q = 0; q < Gv * 3; q++) gr[q] = 0.f;

    // Iteration 0 (peeled: halo zero-fill + l<7 mask live only here)
    pass1_iter<true>(tid, dtr, xr0, xr1, ktr, sat, sap, gr);
    // Iterations 1..3 (guard-free)
#pragma unroll 1
    for (int i = 1; i < ITERS; i++)
        pass1_iter<false>(tid + i * TPB, dtr, xr0, xr1, ktr, sat, sap, gr);

    // ---- block reduction of 6 Gram scalars ----
#pragma unroll
    for (int q = 0; q < Gv * 3; q++) {
        float v = gr[q];
#pragma unroll
        for (int o = 16; o > 0; o >>= 1)
            v += __shfl_xor_sync(0xffffffffu, v, o);
        if (lid == 0) sred[wid][q] = v;
    }
    __syncthreads();
    if (tid < Gv) {
        float G00 = 0.f, G01 = 0.f, G11 = 0.f;
#pragma unroll
        for (int wq = 0; wq < 8; wq++) {
            G00 += sred[wq][tid * 3 + 0];
            G01 += sred[wq][tid * 3 + 1];
            G11 += sred[wq][tid * 3 + 2];
        }
        // scores row0 = softmax([G00,G01]); row1 = softmax([G01,G11])
        // out = 0.5*((s00+s10)*at + ((1-s00)+(1-s10))*ap)
        float s00 = 1.0f / (1.0f + __expf(G01 - G00));
        float s10 = 1.0f / (1.0f + __expf(G11 - G01));
        scoef[tid][0] = 0.5f * (s00 + s10);
        scoef[tid][1] = 0.5f * ((1.0f - s00) + (1.0f - s10));
    }
    __syncthreads();

    // ---- pass 2: out = ca*at + cb*ap (LDS.128 -> STG.128) ----
#pragma unroll
    for (int g = 0; g < Gv; g++) {
        const float ca = scoef[g][0];
        const float cb = scoef[g][1];
        float4* orow = (float4*)(out + (size_t)(b * Cv + c0 + g) * Lv);
#pragma unroll
        for (int i = 0; i < ITERS; i++) {
            const int j = tid + i * TPB;
            float4 a = sat[g * NJ + j];
            float4 p = sap[g * NJ + j];
            float4 o;
            o.x = fmaf(ca, a.x, cb * p.x);
            o.y = fmaf(ca, a.y, cb * p.y);
            o.z = fmaf(ca, a.z, cb * p.z);
            o.w = fmaf(ca, a.w, cb * p.w);
            orow[j] = o;
        }
    }
}

// ---------------------------------------------------------------------------
extern "C" void kernel_launch(void* const* d_in, const int* in_sizes, int n_in,
                              void* d_out, int out_size) {
    const float* x  = (const float*)d_in[0];   // (B, C, L) f32
    const float* dt = (const float*)d_in[1];   // (B, L)    f32
    const float* kt = (const float*)d_in[2];   // (1, 1, K) f32
    float* out = (float*)d_out;                // (B, C, L) f32

    cudaFuncSetAttribute(fused_kernel,
                         cudaFuncAttributeMaxDynamicSharedMemorySize, SMEM_BYTES);

    fused_kernel<<<Bv * Cv / Gv, TPB, SMEM_BYTES>>>(x, dt, kt, out);
}